// round 14
// baseline (speedup 1.0000x reference)
#include <cuda_runtime.h>
#include <cuda_bf16.h>
#include <stdint.h>
#include <math.h>

#define HID 128
#define MAXN 100352
#define MAXE 1664000

// ---------------- scratch (device globals: no allocation allowed) ----------------
__device__ __align__(16) float g_X  [(size_t)MAXN * HID];
__device__ __align__(16) float g_AGG[(size_t)MAXN * HID];
__device__ float g_dis[MAXN];
__device__ int   g_cnt[MAXN];
__device__ int   g_off[MAXN];
__device__ int   g_cur[MAXN];
__device__ int   g_bsum[128];
__device__ int   g_bsum_ex[128];
__device__ int   g_esrc[MAXE];
// bf16 hi/lo weight splits, transposed to [n][k]
__device__ __align__(16) __nv_bfloat16 g_Wga_hi[128 * 256];
__device__ __align__(16) __nv_bfloat16 g_Wga_lo[128 * 256];
__device__ __align__(16) __nv_bfloat16 g_Wf_hi [128 * 256];
__device__ __align__(16) __nv_bfloat16 g_Wf_lo [128 * 256];
__device__ __align__(16) __nv_bfloat16 g_Wp_hi [128 * 64];
__device__ __align__(16) __nv_bfloat16 g_Wp_lo [128 * 64];
__device__ __align__(16) __nv_bfloat16 g_Wg_hi [128 * 128];
__device__ __align__(16) __nv_bfloat16 g_Wg_lo [128 * 128];

// ---------------- mma helpers (baseline PTX, works on plain sm_103) ----------------
__device__ __forceinline__ uint32_t smem_u32(const void* p) {
    uint32_t a;
    asm("{.reg .u64 t; cvta.to.shared.u64 t, %1; cvt.u32.u64 %0, t;}" : "=r"(a) : "l"(p));
    return a;
}
__device__ __forceinline__ void ldm4(uint32_t* r, uint32_t addr) {
    asm volatile("ldmatrix.sync.aligned.m8n8.x4.shared.b16 {%0,%1,%2,%3}, [%4];"
                 : "=r"(r[0]), "=r"(r[1]), "=r"(r[2]), "=r"(r[3]) : "r"(addr));
}
__device__ __forceinline__ void mma_bf16(float* d, const uint32_t* a,
                                         uint32_t b0, uint32_t b1) {
    asm volatile(
        "mma.sync.aligned.m16n8k16.row.col.f32.bf16.bf16.f32 "
        "{%0,%1,%2,%3}, {%4,%5,%6,%7}, {%8,%9}, {%0,%1,%2,%3};"
        : "+f"(d[0]), "+f"(d[1]), "+f"(d[2]), "+f"(d[3])
        : "r"(a[0]), "r"(a[1]), "r"(a[2]), "r"(a[3]), "r"(b0), "r"(b1));
}
__device__ __forceinline__ uint32_t pkbf(float a, float b) {
    __nv_bfloat162 t = __floats2bfloat162_rn(a, b);
    return *(uint32_t*)&t;
}
__device__ __forceinline__ void split8(const float* v, uint32_t* hi, uint32_t* lo) {
#pragma unroll
    for (int t = 0; t < 4; t++) {
        float h0 = __bfloat162float(__float2bfloat16(v[2*t]));
        float h1 = __bfloat162float(__float2bfloat16(v[2*t+1]));
        hi[t] = pkbf(v[2*t], v[2*t+1]);
        lo[t] = pkbf(v[2*t] - h0, v[2*t+1] - h1);
    }
}

// ---- gate_fuse smem layout ----
#define SA 264
#define SB 136
#define A_HI 0u
#define A_LO 67584u
#define B_HI 135168u
#define B_LO 169984u
#define SMEM_BYTES 204800

// ---- proj_gcn smem layout ----
#define SAE 72      // event A row stride (elems); 144B % 128 == 16 -> conflict-free
#define SE1 136     // E1 / Wg row stride (elems); 272B % 128 == 16
#define AEV_HI 0u
#define AEV_LO 18432u
#define E1_HI  36864u
#define E1_LO  71680u
#define PB_HI  106496u
#define PB_LO  141312u
#define SMEM_PG 176128

// ================= W split prep (transpose to [n][k], bf16 hi/lo) =================
__global__ void prep_w(const float* __restrict__ Wga, const float* __restrict__ Wf,
                       const float* __restrict__ Wp,  const float* __restrict__ Wg) {
    int i = blockIdx.x * blockDim.x + threadIdx.x;
    if (i < 256 * 128) {
        int k = i >> 7, n = i & 127;
        {
            float w = Wga[k * 128 + n];
            __nv_bfloat16 h = __float2bfloat16(w);
            g_Wga_hi[n * 256 + k] = h;
            g_Wga_lo[n * 256 + k] = __float2bfloat16(w - __bfloat162float(h));
        }
        {
            float w = Wf[k * 128 + n];
            __nv_bfloat16 h = __float2bfloat16(w);
            g_Wf_hi[n * 256 + k] = h;
            g_Wf_lo[n * 256 + k] = __float2bfloat16(w - __bfloat162float(h));
        }
        if (k < 64) {
            float w = Wp[k * 128 + n];
            __nv_bfloat16 h = __float2bfloat16(w);
            g_Wp_hi[n * 64 + k] = h;
            g_Wp_lo[n * 64 + k] = __float2bfloat16(w - __bfloat162float(h));
        }
        if (k < 128) {   // FIX: was unguarded -> OOB read of Wg + corruption of g_Wg rows
            float w = Wg[k * 128 + n];
            __nv_bfloat16 h = __float2bfloat16(w);
            g_Wg_hi[n * 128 + k] = h;
            g_Wg_lo[n * 128 + k] = __float2bfloat16(w - __bfloat162float(h));
        }
    }
}

// ================= HMMA PROJ + GCN =================
// E1 = relu(ev @ Wp + bp); X = E1 @ Wg  -> g_X (fp32, no bias)
__global__ void __launch_bounds__(256, 1) proj_gcn_mma(
    const float* __restrict__ ev, const float* __restrict__ bp, int N)
{
    extern __shared__ char sm[];
    const uint32_t sb = smem_u32(sm);
    const int tid = threadIdx.x;
    const int wid = tid >> 5;
    const int lane = tid & 31;
    const int m0 = wid * 16;
    const int row0 = blockIdx.x * 128;

    // ---- stage event tile [128 x 64] as bf16 hi/lo ----
    for (int idx = tid; idx < 128 * 8; idx += 256) {
        int r = idx >> 3, c0 = (idx & 7) * 8;
        int row = row0 + r;
        float v[8];
        if (row < N) {
            float4 a = *(const float4*)(ev + (size_t)row * 64 + c0);
            float4 b = *(const float4*)(ev + (size_t)row * 64 + c0 + 4);
            v[0]=a.x; v[1]=a.y; v[2]=a.z; v[3]=a.w; v[4]=b.x; v[5]=b.y; v[6]=b.z; v[7]=b.w;
        } else {
            for (int t = 0; t < 8; t++) v[t] = 0.f;
        }
        uint32_t hi[4], lo[4];
        split8(v, hi, lo);
        uint32_t off = (uint32_t)r * (SAE * 2) + c0 * 2;
        *(uint4*)(sm + AEV_HI + off) = make_uint4(hi[0], hi[1], hi[2], hi[3]);
        *(uint4*)(sm + AEV_LO + off) = make_uint4(lo[0], lo[1], lo[2], lo[3]);
    }
    // ---- stage Wp^T [128n x 64k] hi/lo ----
    for (int idx = tid; idx < 128 * 8; idx += 256) {
        int n = idx >> 3, c0 = (idx & 7) * 8;
        uint32_t off = (uint32_t)n * (SAE * 2) + c0 * 2;
        *(uint4*)(sm + PB_HI + off) = *(const uint4*)(g_Wp_hi + n * 64 + c0);
        *(uint4*)(sm + PB_LO + off) = *(const uint4*)(g_Wp_lo + n * 64 + c0);
    }
    __syncthreads();

    float d[16][4];
#pragma unroll
    for (int t = 0; t < 16; t++)
        for (int q = 0; q < 4; q++) d[t][q] = 0.f;

    const int bn  = (lane & 7) + ((lane >> 4) << 3);
    const int bko = ((lane >> 3) & 1) << 3;
    const int ar  = m0 + (lane & 15);
    const int ako = (lane >> 4) << 3;

    // ---- PROJ GEMM: K=64 over event tile ----
#pragma unroll
    for (int ks = 0; ks < 4; ks++) {
        uint32_t ah[4], al[4];
        uint32_t aaddr = sb + AEV_HI + (uint32_t)ar * (SAE * 2) + (ks * 16 + ako) * 2;
        ldm4(ah, aaddr);
        ldm4(al, aaddr + (AEV_LO - AEV_HI));
#pragma unroll
        for (int np = 0; np < 8; np++) {
            uint32_t baddr = sb + PB_HI + (uint32_t)(np * 16 + bn) * (SAE * 2) + (ks * 16 + bko) * 2;
            uint32_t bh[4], bl[4];
            ldm4(bh, baddr);
            ldm4(bl, baddr + (PB_LO - PB_HI));
            mma_bf16(d[2*np],   ah, bh[0], bh[1]);
            mma_bf16(d[2*np],   al, bh[0], bh[1]);
            mma_bf16(d[2*np],   ah, bl[0], bl[1]);
            mma_bf16(d[2*np+1], ah, bh[2], bh[3]);
            mma_bf16(d[2*np+1], al, bh[2], bh[3]);
            mma_bf16(d[2*np+1], ah, bl[2], bl[3]);
        }
    }
    __syncthreads();  // all reads of PB done before overwrite

    // ---- proj epilogue: relu(d + bp) -> E1 smem (bf16 hi/lo) ----
    {
        int ra = m0 + (lane >> 2);
        int ca = 2 * (lane & 3);
#pragma unroll
        for (int nt = 0; nt < 16; nt++) {
            int n0 = nt * 8 + ca;
            float2 bb2 = *(const float2*)(bp + n0);
            {
                float c0 = fmaxf(d[nt][0] + bb2.x, 0.f);
                float c1 = fmaxf(d[nt][1] + bb2.y, 0.f);
                float h0 = __bfloat162float(__float2bfloat16(c0));
                float h1 = __bfloat162float(__float2bfloat16(c1));
                uint32_t off = (uint32_t)ra * (SE1 * 2) + n0 * 2;
                *(uint32_t*)(sm + E1_HI + off) = pkbf(c0, c1);
                *(uint32_t*)(sm + E1_LO + off) = pkbf(c0 - h0, c1 - h1);
            }
            {
                float c0 = fmaxf(d[nt][2] + bb2.x, 0.f);
                float c1 = fmaxf(d[nt][3] + bb2.y, 0.f);
                float h0 = __bfloat162float(__float2bfloat16(c0));
                float h1 = __bfloat162float(__float2bfloat16(c1));
                uint32_t off = (uint32_t)(ra + 8) * (SE1 * 2) + n0 * 2;
                *(uint32_t*)(sm + E1_HI + off) = pkbf(c0, c1);
                *(uint32_t*)(sm + E1_LO + off) = pkbf(c0 - h0, c1 - h1);
            }
            d[nt][0] = d[nt][1] = d[nt][2] = d[nt][3] = 0.f;
        }
    }
    // ---- stage Wg^T [128n x 128k] hi/lo into PB ----
    for (int idx = tid; idx < 128 * 16; idx += 256) {
        int n = idx >> 4, c0 = (idx & 15) * 8;
        uint32_t off = (uint32_t)n * (SE1 * 2) + c0 * 2;
        *(uint4*)(sm + PB_HI + off) = *(const uint4*)(g_Wg_hi + n * 128 + c0);
        *(uint4*)(sm + PB_LO + off) = *(const uint4*)(g_Wg_lo + n * 128 + c0);
    }
    __syncthreads();

    // ---- GCN GEMM: K=128 over E1 ----
#pragma unroll
    for (int ks = 0; ks < 8; ks++) {
        uint32_t ah[4], al[4];
        uint32_t aaddr = sb + E1_HI + (uint32_t)ar * (SE1 * 2) + (ks * 16 + ako) * 2;
        ldm4(ah, aaddr);
        ldm4(al, aaddr + (E1_LO - E1_HI));
#pragma unroll
        for (int np = 0; np < 8; np++) {
            uint32_t baddr = sb + PB_HI + (uint32_t)(np * 16 + bn) * (SE1 * 2) + (ks * 16 + bko) * 2;
            uint32_t bh[4], bl[4];
            ldm4(bh, baddr);
            ldm4(bl, baddr + (PB_LO - PB_HI));
            mma_bf16(d[2*np],   ah, bh[0], bh[1]);
            mma_bf16(d[2*np],   al, bh[0], bh[1]);
            mma_bf16(d[2*np],   ah, bl[0], bl[1]);
            mma_bf16(d[2*np+1], ah, bh[2], bh[3]);
            mma_bf16(d[2*np+1], al, bh[2], bh[3]);
            mma_bf16(d[2*np+1], ah, bl[2], bl[3]);
        }
    }

    // ---- write X (fp32, no bias) ----
    {
        int ra = m0 + (lane >> 2);
        int ca = 2 * (lane & 3);
        int gra = row0 + ra;
        int grb = gra + 8;
#pragma unroll
        for (int nt = 0; nt < 16; nt++) {
            int n0 = nt * 8 + ca;
            if (gra < N)
                *(float2*)(&g_X[(size_t)gra * HID + n0]) = make_float2(d[nt][0], d[nt][1]);
            if (grb < N)
                *(float2*)(&g_X[(size_t)grb * HID + n0]) = make_float2(d[nt][2], d[nt][3]);
        }
    }
}

// ================= HMMA GATE+FUSE (validated round 11) =================
__global__ void __launch_bounds__(256, 1) gate_fuse_mma(
    const float* __restrict__ base, const float* __restrict__ bga,
    const float* __restrict__ bgcn, const float* __restrict__ bf,
    float* __restrict__ outp, int N)
{
    extern __shared__ char sm[];
    const uint32_t sb = smem_u32(sm);
    const int tid = threadIdx.x;
    const int wid = tid >> 5;
    const int lane = tid & 31;
    const int m0 = wid * 16;
    const int row0 = blockIdx.x * 128;

    for (int idx = tid; idx < 128 * 32; idx += 256) {
        int r = idx >> 5, c0 = (idx & 31) * 8;
        int row = row0 + r;
        float v[8];
        if (row < N) {
            if (c0 < 128) {
                float4 a = *(const float4*)(base + (size_t)row * HID + c0);
                float4 b = *(const float4*)(base + (size_t)row * HID + c0 + 4);
                v[0]=a.x; v[1]=a.y; v[2]=a.z; v[3]=a.w; v[4]=b.x; v[5]=b.y; v[6]=b.z; v[7]=b.w;
            } else {
                int j = c0 - 128;
                float4 a = *(const float4*)(&g_AGG[(size_t)row * HID + j]);
                float4 b = *(const float4*)(&g_AGG[(size_t)row * HID + j + 4]);
                float4 c = *(const float4*)(bgcn + j);
                float4 d = *(const float4*)(bgcn + j + 4);
                v[0]=fmaxf(a.x+c.x,0.f); v[1]=fmaxf(a.y+c.y,0.f);
                v[2]=fmaxf(a.z+c.z,0.f); v[3]=fmaxf(a.w+c.w,0.f);
                v[4]=fmaxf(b.x+d.x,0.f); v[5]=fmaxf(b.y+d.y,0.f);
                v[6]=fmaxf(b.z+d.z,0.f); v[7]=fmaxf(b.w+d.w,0.f);
            }
        } else {
            for (int t = 0; t < 8; t++) v[t] = 0.f;
        }
        uint32_t hi[4], lo[4];
        split8(v, hi, lo);
        uint32_t off = (uint32_t)r * (SA * 2) + c0 * 2;
        *(uint4*)(sm + A_HI + off) = make_uint4(hi[0], hi[1], hi[2], hi[3]);
        *(uint4*)(sm + A_LO + off) = make_uint4(lo[0], lo[1], lo[2], lo[3]);
    }

    auto stageB = [&](const __nv_bfloat16* Wh, const __nv_bfloat16* Wl, int kh) {
        for (int idx = tid; idx < 128 * 16; idx += 256) {
            int n = idx >> 4, c0 = (idx & 15) * 8;
            uint32_t off = (uint32_t)n * (SB * 2) + c0 * 2;
            *(uint4*)(sm + B_HI + off) = *(const uint4*)(Wh + n * 256 + kh * 128 + c0);
            *(uint4*)(sm + B_LO + off) = *(const uint4*)(Wl + n * 256 + kh * 128 + c0);
        }
    };

    float d[16][4];
#pragma unroll
    for (int t = 0; t < 16; t++)
        for (int q = 0; q < 4; q++) d[t][q] = 0.f;

    auto gemm_half = [&](int kh) {
        int bn = (lane & 7) + ((lane >> 4) << 3);
        int bko = ((lane >> 3) & 1) << 3;
        int ar = m0 + (lane & 15);
        int ako = (lane >> 4) << 3;
#pragma unroll
        for (int ks = 0; ks < 8; ks++) {
            uint32_t ah[4], al[4];
            uint32_t aaddr = sb + A_HI + (uint32_t)ar * (SA * 2) + (kh * 128 + ks * 16 + ako) * 2;
            ldm4(ah, aaddr);
            ldm4(al, aaddr + (A_LO - A_HI));
#pragma unroll
            for (int np = 0; np < 8; np++) {
                uint32_t baddr = sb + B_HI + (uint32_t)(np * 16 + bn) * (SB * 2) + (ks * 16 + bko) * 2;
                uint32_t bh[4], bl[4];
                ldm4(bh, baddr);
                ldm4(bl, baddr + (B_LO - B_HI));
                mma_bf16(d[2*np],   ah, bh[0], bh[1]);
                mma_bf16(d[2*np],   al, bh[0], bh[1]);
                mma_bf16(d[2*np],   ah, bl[0], bl[1]);
                mma_bf16(d[2*np+1], ah, bh[2], bh[3]);
                mma_bf16(d[2*np+1], al, bh[2], bh[3]);
                mma_bf16(d[2*np+1], ah, bl[2], bl[3]);
            }
        }
    };

    stageB(g_Wga_hi, g_Wga_lo, 0);
    __syncthreads();
    gemm_half(0);
    __syncthreads();
    stageB(g_Wga_hi, g_Wga_lo, 1);
    __syncthreads();
    gemm_half(1);
    __syncthreads();

    {
        int ra = m0 + (lane >> 2);
        int ca = 2 * (lane & 3);
        int gra = row0 + ra;
        int grb = gra + 8;
#pragma unroll
        for (int nt = 0; nt < 16; nt++) {
            int n0 = nt * 8 + ca;
            float2 bb2 = *(const float2*)(bga + n0);
            float2 bg2 = *(const float2*)(bgcn + n0);
            if (gra < N) {
                float2 bs = *(const float2*)(base + (size_t)gra * HID + n0);
                float2 ag = *(const float2*)(&g_AGG[(size_t)gra * HID + n0]);
                float dv0 = fmaxf(ag.x + bg2.x, 0.f), dv1 = fmaxf(ag.y + bg2.y, 0.f);
                float g0 = 1.f / (1.f + __expf(-(d[nt][0] + bb2.x)));
                float g1 = 1.f / (1.f + __expf(-(d[nt][1] + bb2.y)));
                float c0 = bs.x * (1.f - g0) + dv0 * g0;
                float c1 = bs.y * (1.f - g1) + dv1 * g1;
                float h0 = __bfloat162float(__float2bfloat16(c0));
                float h1 = __bfloat162float(__float2bfloat16(c1));
                uint32_t off = (uint32_t)ra * (SA * 2) + (128 + n0) * 2;
                *(uint32_t*)(sm + A_HI + off) = pkbf(c0, c1);
                *(uint32_t*)(sm + A_LO + off) = pkbf(c0 - h0, c1 - h1);
            }
            if (grb < N) {
                float2 bs = *(const float2*)(base + (size_t)grb * HID + n0);
                float2 ag = *(const float2*)(&g_AGG[(size_t)grb * HID + n0]);
                float dv0 = fmaxf(ag.x + bg2.x, 0.f), dv1 = fmaxf(ag.y + bg2.y, 0.f);
                float g0 = 1.f / (1.f + __expf(-(d[nt][2] + bb2.x)));
                float g1 = 1.f / (1.f + __expf(-(d[nt][3] + bb2.y)));
                float c0 = bs.x * (1.f - g0) + dv0 * g0;
                float c1 = bs.y * (1.f - g1) + dv1 * g1;
                float h0 = __bfloat162float(__float2bfloat16(c0));
                float h1 = __bfloat162float(__float2bfloat16(c1));
                uint32_t off = (uint32_t)(ra + 8) * (SA * 2) + (128 + n0) * 2;
                *(uint32_t*)(sm + A_HI + off) = pkbf(c0, c1);
                *(uint32_t*)(sm + A_LO + off) = pkbf(c0 - h0, c1 - h1);
            }
            d[nt][0] = d[nt][1] = d[nt][2] = d[nt][3] = 0.f;
        }
    }
    stageB(g_Wf_hi, g_Wf_lo, 0);
    __syncthreads();

    gemm_half(0);
    __syncthreads();
    stageB(g_Wf_hi, g_Wf_lo, 1);
    __syncthreads();
    gemm_half(1);

    {
        int ra = m0 + (lane >> 2);
        int ca = 2 * (lane & 3);
        int gra = row0 + ra;
        int grb = gra + 8;
#pragma unroll
        for (int nt = 0; nt < 16; nt++) {
            int n0 = nt * 8 + ca;
            float2 bb2 = *(const float2*)(bf + n0);
            if (gra < N) {
                float2 o;
                o.x = fmaxf(d[nt][0] + bb2.x, 0.f);
                o.y = fmaxf(d[nt][1] + bb2.y, 0.f);
                *(float2*)(outp + (size_t)gra * HID + n0) = o;
            }
            if (grb < N) {
                float2 o;
                o.x = fmaxf(d[nt][2] + bb2.x, 0.f);
                o.y = fmaxf(d[nt][3] + bb2.y, 0.f);
                *(float2*)(outp + (size_t)grb * HID + n0) = o;
            }
        }
    }
}

// ---------------- CSR build ----------------
__global__ void zero_cnt(int N) {
    int i = blockIdx.x * blockDim.x + threadIdx.x;
    if (i < N) g_cnt[i] = 0;
}
__global__ void hist(const int* __restrict__ dst, int E, int N) {
    for (int e = blockIdx.x * blockDim.x + threadIdx.x; e < E;
         e += gridDim.x * blockDim.x) {
        unsigned d = (unsigned)dst[e];
        if (d < (unsigned)N) atomicAdd(&g_cnt[d], 1);
    }
}
__global__ void scan1(int N) {
    __shared__ int sm1[1024];
    int i = blockIdx.x * 1024 + threadIdx.x;
    int v = (i < N) ? g_cnt[i] : 0;
    sm1[threadIdx.x] = v;
    __syncthreads();
#pragma unroll
    for (int ofs = 1; ofs < 1024; ofs <<= 1) {
        int t = (threadIdx.x >= ofs) ? sm1[threadIdx.x - ofs] : 0;
        __syncthreads();
        sm1[threadIdx.x] += t;
        __syncthreads();
    }
    if (i < N) g_off[i] = sm1[threadIdx.x] - v;
    if (threadIdx.x == 1023) g_bsum[blockIdx.x] = sm1[1023];
}
__global__ void scan2(int nb) {
    __shared__ int sm2[128];
    int v = (threadIdx.x < nb) ? g_bsum[threadIdx.x] : 0;
    sm2[threadIdx.x] = v;
    __syncthreads();
#pragma unroll
    for (int ofs = 1; ofs < 128; ofs <<= 1) {
        int t = (threadIdx.x >= ofs) ? sm2[threadIdx.x - ofs] : 0;
        __syncthreads();
        sm2[threadIdx.x] += t;
        __syncthreads();
    }
    if (threadIdx.x < nb) g_bsum_ex[threadIdx.x] = sm2[threadIdx.x] - v;
}
__global__ void scan3(int N) {
    int i = blockIdx.x * 1024 + threadIdx.x;
    if (i >= N) return;
    int o = g_off[i] + g_bsum_ex[blockIdx.x];
    g_off[i] = o;
    g_cur[i] = o;
    g_dis[i] = rsqrtf((float)(g_cnt[i] + 1));
}
__global__ void fill_csr(const int* __restrict__ src,
                         const int* __restrict__ dst, int E, int N) {
    for (int e = blockIdx.x * blockDim.x + threadIdx.x; e < E;
         e += gridDim.x * blockDim.x) {
        unsigned d = (unsigned)dst[e];
        unsigned s = (unsigned)src[e];
        if (d < (unsigned)N && s < (unsigned)N) {
            int pos = atomicAdd(&g_cur[d], 1);
            if (pos < MAXE) g_esrc[pos] = (int)s;
        }
    }
}

// ---------------- aggregation ----------------
__global__ void __launch_bounds__(256) aggregate(int N) {
    int warp = (blockIdx.x * blockDim.x + threadIdx.x) >> 5;
    int lane = threadIdx.x & 31;
    if (warp >= N) return;
    int node = warp;
    float dd = g_dis[node];
    float inv = dd * dd;

    float4 acc = *(const float4*)(&g_X[(size_t)node * HID + lane * 4]);
    acc.x *= inv; acc.y *= inv; acc.z *= inv; acc.w *= inv;

    int beg = g_off[node];
    int end = beg + g_cnt[node];
    int i = beg;
    for (; i + 2 <= end; i += 2) {
        int s0 = g_esrc[i];
        int s1 = g_esrc[i + 1];
        float n0 = g_dis[s0] * dd;
        float n1 = g_dis[s1] * dd;
        float4 v0 = *(const float4*)(&g_X[(size_t)s0 * HID + lane * 4]);
        float4 v1 = *(const float4*)(&g_X[(size_t)s1 * HID + lane * 4]);
        acc.x = fmaf(v0.x, n0, acc.x);
        acc.y = fmaf(v0.y, n0, acc.y);
        acc.z = fmaf(v0.z, n0, acc.z);
        acc.w = fmaf(v0.w, n0, acc.w);
        acc.x = fmaf(v1.x, n1, acc.x);
        acc.y = fmaf(v1.y, n1, acc.y);
        acc.z = fmaf(v1.z, n1, acc.z);
        acc.w = fmaf(v1.w, n1, acc.w);
    }
    if (i < end) {
        int s = g_esrc[i];
        float nrm = g_dis[s] * dd;
        float4 v = *(const float4*)(&g_X[(size_t)s * HID + lane * 4]);
        acc.x = fmaf(v.x, nrm, acc.x);
        acc.y = fmaf(v.y, nrm, acc.y);
        acc.z = fmaf(v.z, nrm, acc.z);
        acc.w = fmaf(v.w, nrm, acc.w);
    }
    *(float4*)(&g_AGG[(size_t)node * HID + lane * 4]) = acc;
}

// ---------------- launch ----------------
extern "C" void kernel_launch(void* const* d_in, const int* in_sizes, int n_in,
                              void* d_out, int out_size) {
    const float* base = (const float*)d_in[0];
    const float* ev   = (const float*)d_in[1];
    const int*   ei   = (const int*)d_in[2];
    const float* Wp = (const float*)d_in[3];
    const float* bp = (const float*)d_in[4];
    const float* Wg = (const float*)d_in[5];
    const float* bg = (const float*)d_in[6];
    const float* Wga = (const float*)d_in[7];
    const float* bga = (const float*)d_in[8];
    const float* Wf = (const float*)d_in[9];
    const float* bf = (const float*)d_in[10];
    float* out = (float*)d_out;

    const int N = in_sizes[0] / HID;
    const int E = in_sizes[2] / 2;
    const int* src = ei;
    const int* dst = ei + E;
    const int nb = (N + 1023) / 1024;

    cudaFuncSetAttribute(gate_fuse_mma, cudaFuncAttributeMaxDynamicSharedMemorySize,
                         SMEM_BYTES);
    cudaFuncSetAttribute(proj_gcn_mma, cudaFuncAttributeMaxDynamicSharedMemorySize,
                         SMEM_PG);

    prep_w<<<128, 256>>>(Wga, Wf, Wp, Wg);
    proj_gcn_mma<<<(N + 127) / 128, 256, SMEM_PG>>>(ev, bp, N);
    zero_cnt<<<(N + 255) / 256, 256>>>(N);
    hist<<<2368, 256>>>(dst, E, N);
    scan1<<<nb, 1024>>>(N);
    scan2<<<1, 128>>>(nb);
    scan3<<<nb, 1024>>>(N);
    fill_csr<<<2368, 256>>>(src, dst, E, N);
    aggregate<<<(N * 32 + 255) / 256, 256>>>(N);
    gate_fuse_mma<<<(N + 127) / 128, 256, SMEM_BYTES>>>(base, bga, bg, bf, out, N);
}